// round 3
// baseline (speedup 1.0000x reference)
#include <cuda_runtime.h>
#include <math.h>
#include <stdint.h>

// ============================================================================
// DyGNN streaming scan -> wave-parallel batched GEMMs.
//
// Events conflict only when they share a node id (4096 touches over 100000
// nodes => sparse conflicts, dependency depth ~<=8). A scheduler kernel sorts
// touches, builds predecessor links, computes wave levels, and buckets steps
// into waves. A persistent cooperative kernel then processes each wave as
// batched GEMMs over compact copy-on-gather state tables.
// ============================================================================

#define MAXS   2048
#define NTOUCH 4096
#define NBLK   148
#define NTHR   256

#define EPI_NONE 0
#define EPI_TANH 1
#define EPI_CADJ 2

struct Params {
  const int   *heads, *tails;
  const float *times;
  const float *node_rep, *cell_head, *hidden_head, *cell_tail, *hidden_tail;
  const float *Weh1, *Weh2, *beh, *Wet1, *Wet2, *bet;
  const float *Wxh, *Whh, *bh, *Wdh, *bdh;
  const float *Wxt, *Wht, *bt, *Wdt, *bdt;
  const float *Wc1, *Wc2;
  float *out;
  int S;
};

// ---------------- scheduler outputs ----------------
__device__ int g_cidH[MAXS], g_cidT[MAXS];
__device__ int g_predH[MAXS], g_predT[MAXS];
__device__ int g_cidNode[NTOUCH];
__device__ int g_nCompact;
__device__ int g_stepList[MAXS];
__device__ int g_waveOff[MAXS + 2];
__device__ int g_waveCnt[MAXS + 2];
__device__ int g_numWaves;

// ---------------- compact state tables ----------------
__device__ float c_rep[NTOUCH * 128];
__device__ float c_ch [NTOUCH * 128];
__device__ float c_hh [NTOUCH * 128];
__device__ float c_ct [NTOUCH * 128];
__device__ float c_ht [NTOUCH * 128];
__device__ float c_rt [NTOUCH];

// ---------------- per-wave batch buffers ----------------
__device__ float bRepH[MAXS * 128], bRepT[MAXS * 128];
__device__ float bCH  [MAXS * 128], bHH  [MAXS * 128];
__device__ float bCT  [MAXS * 128], bHT  [MAXS * 128];
__device__ float bHTh [MAXS * 128], bHHt [MAXS * 128];
__device__ float bEdgeH[MAXS * 128], bEdgeT[MAXS * 128];
__device__ float bCadjH[MAXS * 128], bCadjT[MAXS * 128];
__device__ float bHnH [MAXS * 128], bHnT [MAXS * 128];
__device__ float bNRH [MAXS * 128], bNRT [MAXS * 128];
__device__ float bZH  [MAXS * 512], bZT  [MAXS * 512];
__device__ float bDecH[MAXS], bDecT[MAXS];

// ---------------- grid barrier state ----------------
__device__ unsigned g_barCnt;            // zero-init
__device__ volatile unsigned g_barGen;   // zero-init

__device__ __forceinline__ void grid_barrier() {
  __syncthreads();
  if (threadIdx.x == 0) {
    unsigned gen = g_barGen;
    __threadfence();
    if (atomicAdd(&g_barCnt, 1u) == gridDim.x - 1) {
      g_barCnt = 0;
      __threadfence();
      g_barGen = gen + 1;
    } else {
      while (g_barGen == gen) { __nanosleep(64); }
    }
    __threadfence();
  }
  __syncthreads();
}

__device__ __forceinline__ float sigf(float x) { return 1.0f / (1.0f + expf(-x)); }

// ============================================================================
// Scheduler: sort touches, compact ids, predecessor links, wave levels.
// Single block, 1024 threads.
// ============================================================================
__global__ void __launch_bounds__(1024) scheduler_kernel(const int* heads, const int* tails, int S) {
  __shared__ unsigned keys[NTOUCH];
  __shared__ int part[1024];
  __shared__ volatile int lvl[MAXS];
  __shared__ int sChanged;
  __shared__ int sMax;

  const int tid = threadIdx.x;
  const int T = 2 * S;

  // 1) build keys: key = node*8192 + seq (seq = step*2 + isTail)
  for (int i = tid; i < NTOUCH; i += 1024) {
    if (i < T) {
      int step = i >> 1; int isT = i & 1;
      unsigned node = (unsigned)(isT ? tails[step] : heads[step]);
      keys[i] = node * 8192u + (unsigned)i;
    } else {
      keys[i] = 0xFFFFFFFFu;
    }
  }
  __syncthreads();

  // 2) bitonic sort (ascending)
  for (unsigned k = 2; k <= NTOUCH; k <<= 1) {
    for (unsigned j = k >> 1; j > 0; j >>= 1) {
      for (unsigned i = tid; i < NTOUCH; i += 1024) {
        unsigned ixj = i ^ j;
        if (ixj > i) {
          bool asc = ((i & k) == 0);
          unsigned a = keys[i], b = keys[ixj];
          if ((a > b) == asc) { keys[i] = b; keys[ixj] = a; }
        }
      }
      __syncthreads();
    }
  }

  // 3) compact ids via prefix scan of "new node" flags
  const int base = tid * 4;
  int loc[4]; int sum = 0;
  for (int j = 0; j < 4; j++) {
    int p = base + j;
    int f = 0;
    if (p < T) {
      unsigned nd = keys[p] >> 13;
      f = (p == 0) ? 1 : ((keys[p - 1] >> 13) != nd);
    }
    loc[j] = sum; sum += f;
  }
  part[tid] = sum;
  __syncthreads();
  for (int off = 1; off < 1024; off <<= 1) {
    int add = (tid >= off) ? part[tid - off] : 0;
    __syncthreads();
    part[tid] += add;
    __syncthreads();
  }
  int prev = (tid == 0) ? 0 : part[tid - 1];

  for (int j = 0; j < 4; j++) {
    int p = base + j;
    if (p < T) {
      unsigned key = keys[p];
      unsigned nd = key >> 13;
      int seq = (int)(key & 8191u);
      int step = seq >> 1, isT = seq & 1;
      int f = (p == 0) ? 1 : ((keys[p - 1] >> 13) != nd);
      int cid = prev + loc[j] + f - 1;
      if (f) g_cidNode[cid] = (int)nd;
      if (isT) g_cidT[step] = cid; else g_cidH[step] = cid;
      // nearest earlier touch of same node in a DIFFERENT step
      int pred = -1;
      if (p > 0 && (keys[p - 1] >> 13) == nd) {
        int ps = (int)((keys[p - 1] & 8191u) >> 1);
        if (ps != step) pred = ps;
        else if (p > 1 && (keys[p - 2] >> 13) == nd)
          pred = (int)((keys[p - 2] & 8191u) >> 1);
      }
      if (isT) g_predT[step] = pred; else g_predH[step] = pred;
    }
  }
  if (tid == 0) g_nCompact = part[1023];
  __syncthreads();

  // 4) wave levels (Bellman-Ford style relaxation; preds always earlier steps)
  for (int s = tid; s < S; s += 1024) lvl[s] = 1;
  if (tid == 0) { sMax = 1; }
  __syncthreads();
  for (int pass = 0; pass < S + 2; ++pass) {
    if (tid == 0) sChanged = 0;
    __syncthreads();
    for (int s = tid; s < S; s += 1024) {
      int ph = g_predH[s], pt = g_predT[s];
      int lp = 0;
      if (ph >= 0) lp = lvl[ph];
      if (pt >= 0) { int v = lvl[pt]; if (v > lp) lp = v; }
      int nl = lp + 1;
      if (nl > lvl[s]) { lvl[s] = nl; sChanged = 1; }
    }
    __syncthreads();
    if (!sChanged) break;
    __syncthreads();
  }

  // 5) max level
  {
    int lm = 0;
    for (int s = tid; s < S; s += 1024) { int v = lvl[s]; if (v > lm) lm = v; }
    atomicMax(&sMax, lm);
  }
  __syncthreads();
  int nW = sMax;
  if (tid == 0) g_numWaves = nW;

  // 6) bucket steps by level
  for (int i = tid; i <= nW; i += 1024) g_waveCnt[i] = 0;
  __syncthreads();
  for (int s = tid; s < S; s += 1024) atomicAdd(&g_waveCnt[lvl[s]], 1);
  __syncthreads();
  if (tid == 0) {
    int acc = 0; g_waveOff[0] = 0;
    for (int l = 1; l <= nW; ++l) { acc += g_waveCnt[l]; g_waveOff[l] = acc; g_waveCnt[l] = 0; }
  }
  __syncthreads();
  for (int s = tid; s < S; s += 1024) {
    int l = lvl[s];
    int pos = g_waveOff[l - 1] + atomicAdd(&g_waveCnt[l], 1);
    g_stepList[pos] = s;
  }
}

// ============================================================================
// Initial gather of touched rows into compact state tables.
// ============================================================================
__global__ void init_state_kernel(const float* rep, const float* ch, const float* hh,
                                  const float* ct, const float* ht) {
  int nC = g_nCompact;
  int total = nC * 128;
  int gsize = gridDim.x * blockDim.x;
  for (int e = blockIdx.x * blockDim.x + threadIdx.x; e < total; e += gsize) {
    int c = e >> 7, d = e & 127;
    int node = g_cidNode[c];
    size_t src = (size_t)node * 128 + d;
    c_rep[e] = rep[src];
    c_ch[e]  = ch[src];
    c_hh[e]  = hh[src];
    c_ct[e]  = ct[src];
    c_ht[e]  = ht[src];
    if (d == 0) c_rt[c] = 0.0f;
  }
}

// ============================================================================
// Tiled fp32 GEMM: C[m0:m0+32, n0:n0+64) = epi(A1@W1 (+ A2@W2) + bias)
// A row-major [M][128], W row-major [128][ldw]. Block-cooperative (256 thr).
// ============================================================================
__device__ void gemm_tile(const float* __restrict__ A1, const float* __restrict__ W1,
                          const float* __restrict__ A2, const float* __restrict__ W2,
                          const float* __restrict__ bias,
                          float* __restrict__ C, int ldw, int ldc,
                          int M, int m0, int n0, int epi,
                          const float* __restrict__ Cprev, const float* __restrict__ dec,
                          float (*As)[33], float (*Ws)[64]) {
  const int t = threadIdx.x;
  const int tr = t >> 4;        // 0..15 -> rows tr*2, tr*2+1
  const int tc = t & 15;        // 0..15 -> cols tc*4 .. tc*4+3

  float acc[2][4];
#pragma unroll
  for (int i = 0; i < 2; i++)
#pragma unroll
    for (int j = 0; j < 4; j++) acc[i][j] = 0.0f;

  const int npair = A2 ? 2 : 1;
  for (int pair = 0; pair < npair; ++pair) {
    const float* A = pair ? A2 : A1;
    const float* W = pair ? W2 : W1;
    for (int k0 = 0; k0 < 128; k0 += 32) {
      // stage A tile 32x32
      for (int i = t; i < 32 * 32; i += NTHR) {
        int r = i >> 5, kk = i & 31;
        int gr = m0 + r;
        As[r][kk] = (gr < M) ? A[(size_t)gr * 128 + k0 + kk] : 0.0f;
      }
      // stage W tile 32x64
      for (int i = t; i < 32 * 64; i += NTHR) {
        int kk = i >> 6, nn = i & 63;
        Ws[kk][nn] = W[(size_t)(k0 + kk) * ldw + n0 + nn];
      }
      __syncthreads();
#pragma unroll
      for (int kk = 0; kk < 32; ++kk) {
        float a0 = As[tr * 2][kk];
        float a1 = As[tr * 2 + 1][kk];
        float4 w = *(const float4*)&Ws[kk][tc * 4];
        acc[0][0] += a0 * w.x; acc[0][1] += a0 * w.y; acc[0][2] += a0 * w.z; acc[0][3] += a0 * w.w;
        acc[1][0] += a1 * w.x; acc[1][1] += a1 * w.y; acc[1][2] += a1 * w.z; acc[1][3] += a1 * w.w;
      }
      __syncthreads();
    }
  }

  // epilogue
#pragma unroll
  for (int i = 0; i < 2; i++) {
    int r = m0 + tr * 2 + i;
    if (r < M) {
#pragma unroll
      for (int j = 0; j < 4; j++) {
        int cc = n0 + tc * 4 + j;
        float v = acc[i][j];
        if (bias) v += bias[cc];
        float outv;
        if (epi == EPI_TANH) {
          outv = tanhf(v);
        } else if (epi == EPI_CADJ) {
          float cs = tanhf(v);
          float cp = Cprev[(size_t)r * 128 + cc];
          outv = cp - cs + cs * dec[r];
        } else {
          outv = v;
        }
        C[(size_t)r * ldc + cc] = outv;
      }
    }
  }
}

// ============================================================================
// Persistent cooperative main kernel.
// ============================================================================
__global__ void __launch_bounds__(NTHR) main_kernel(Params p) {
  __shared__ float As[32][33];
  __shared__ float Ws[32][64];

  const int tid = threadIdx.x;
  const int gsize = gridDim.x * blockDim.x;
  const int gtid = blockIdx.x * blockDim.x + tid;
  const int nW = g_numWaves;
  const int S = p.S;

  for (int w = 1; w <= nW; ++w) {
    const int s0 = g_waveOff[w - 1];
    const int M = g_waveOff[w] - s0;
    const int mT = (M + 31) >> 5;

    // ---- Phase A: gather state, emit outputs, compute decays ----
    for (int e = gtid; e < M * 128; e += gsize) {
      int s = e >> 7, d = e & 127;
      int step = g_stepList[s0 + s];
      int ch = g_cidH[step], ct = g_cidT[step];
      float rh = c_rep[ch * 128 + d];
      float rt = c_rep[ct * 128 + d];
      bRepH[s * 128 + d] = rh;
      bRepT[s * 128 + d] = rt;
      bCH[s * 128 + d] = c_ch[ch * 128 + d];
      bHH[s * 128 + d] = c_hh[ch * 128 + d];
      bCT[s * 128 + d] = c_ct[ct * 128 + d];
      bHT[s * 128 + d] = c_ht[ct * 128 + d];
      bHTh[s * 128 + d] = c_ht[ch * 128 + d];
      bHHt[s * 128 + d] = c_hh[ct * 128 + d];
      p.out[(size_t)step * 128 + d] = rh;
      p.out[(size_t)S * 128 + (size_t)step * 128 + d] = rt;
      if (d == 0) {
        float tm = p.times[step];
        bDecH[s] = expf(-(tm - c_rt[ch]));
        bDecT[s] = expf(-(tm - c_rt[ct]));
      }
    }
    grid_barrier();

    // ---- Phase B: edge updaters + c-adjust GEMMs (N=128) ----
    {
      int tot = mT * 8;
      for (int tIdx = blockIdx.x; tIdx < tot; tIdx += gridDim.x) {
        int mt = tIdx % mT; int rest = tIdx / mT;
        int job = rest >> 1, nt = rest & 1;
        int m0 = mt * 32, n0 = nt * 64;
        if (job == 0)
          gemm_tile(bRepH, p.Weh1, bRepT, p.Weh2, p.beh, bEdgeH, 128, 128, M, m0, n0, EPI_TANH, 0, 0, As, Ws);
        else if (job == 1)
          gemm_tile(bRepH, p.Wet1, bRepT, p.Wet2, p.bet, bEdgeT, 128, 128, M, m0, n0, EPI_TANH, 0, 0, As, Ws);
        else if (job == 2)
          gemm_tile(bCH, p.Wdh, 0, 0, p.bdh, bCadjH, 128, 128, M, m0, n0, EPI_CADJ, bCH, bDecH, As, Ws);
        else
          gemm_tile(bCT, p.Wdt, 0, 0, p.bdt, bCadjT, 128, 128, M, m0, n0, EPI_CADJ, bCT, bDecT, As, Ws);
      }
    }
    grid_barrier();

    // ---- Phase C: LSTM gate GEMMs (N=512) ----
    {
      int tot = mT * 16;
      for (int tIdx = blockIdx.x; tIdx < tot; tIdx += gridDim.x) {
        int mt = tIdx % mT; int rest = tIdx / mT;
        int job = rest >> 3, nt = rest & 7;
        int m0 = mt * 32, n0 = nt * 64;
        if (job == 0)
          gemm_tile(bEdgeH, p.Wxh, bHH, p.Whh, p.bh, bZH, 512, 512, M, m0, n0, EPI_NONE, 0, 0, As, Ws);
        else
          gemm_tile(bEdgeT, p.Wxt, bHT, p.Wht, p.bt, bZT, 512, 512, M, m0, n0, EPI_NONE, 0, 0, As, Ws);
      }
    }
    grid_barrier();

    // ---- Phase D: gates elementwise + cell/hidden scatter ----
    for (int e = gtid; e < M * 128; e += gsize) {
      int s = e >> 7, d = e & 127;
      int step = g_stepList[s0 + s];
      int ch = g_cidH[step], ct = g_cidT[step];
      {
        float zi = bZH[s * 512 + d];
        float zf = bZH[s * 512 + 128 + d];
        float zo = bZH[s * 512 + 256 + d];
        float zg = bZH[s * 512 + 384 + d];
        float ii = sigf(zi), ff = sigf(zf), oo = sigf(zo), gg = tanhf(zg);
        float cn = ff * bCadjH[s * 128 + d] + ii * gg;
        float hn = oo * tanhf(cn);
        bHnH[s * 128 + d] = hn;
        c_ch[ch * 128 + d] = cn;
        c_hh[ch * 128 + d] = hn;
      }
      {
        float zi = bZT[s * 512 + d];
        float zf = bZT[s * 512 + 128 + d];
        float zo = bZT[s * 512 + 256 + d];
        float zg = bZT[s * 512 + 384 + d];
        float ii = sigf(zi), ff = sigf(zf), oo = sigf(zo), gg = tanhf(zg);
        float cn = ff * bCadjT[s * 128 + d] + ii * gg;
        float hn = oo * tanhf(cn);
        bHnT[s * 128 + d] = hn;
        c_ct[ct * 128 + d] = cn;
        c_ht[ct * 128 + d] = hn;
      }
      if (d == 0) {
        float tm = p.times[step];
        c_rt[ch] = tm;
        c_rt[ct] = tm;
      }
    }
    grid_barrier();

    // ---- Phase E: combiner GEMMs ----
    {
      int tot = mT * 4;
      for (int tIdx = blockIdx.x; tIdx < tot; tIdx += gridDim.x) {
        int mt = tIdx % mT; int rest = tIdx / mT;
        int job = rest >> 1, nt = rest & 1;
        int m0 = mt * 32, n0 = nt * 64;
        if (job == 0)
          gemm_tile(bHnH, p.Wc1, bHTh, p.Wc2, 0, bNRH, 128, 128, M, m0, n0, EPI_TANH, 0, 0, As, Ws);
        else
          gemm_tile(bHHt, p.Wc1, bHnT, p.Wc2, 0, bNRT, 128, 128, M, m0, n0, EPI_TANH, 0, 0, As, Ws);
      }
    }
    grid_barrier();

    // ---- Phase E2: rep scatter (head first, tail wins on h==t) ----
    for (int e = gtid; e < M * 128; e += gsize) {
      int s = e >> 7, d = e & 127;
      int step = g_stepList[s0 + s];
      int ch = g_cidH[step], ct = g_cidT[step];
      c_rep[ch * 128 + d] = bNRH[s * 128 + d];
      c_rep[ct * 128 + d] = bNRT[s * 128 + d];   // same thread => ordered
    }
    grid_barrier();
  }
}

// ============================================================================
extern "C" void kernel_launch(void* const* d_in, const int* in_sizes, int n_in,
                              void* d_out, int out_size) {
  Params p;
  p.heads       = (const int*)d_in[0];
  p.tails       = (const int*)d_in[1];
  p.times       = (const float*)d_in[2];
  p.node_rep    = (const float*)d_in[3];
  p.cell_head   = (const float*)d_in[4];
  p.hidden_head = (const float*)d_in[5];
  p.cell_tail   = (const float*)d_in[6];
  p.hidden_tail = (const float*)d_in[7];
  p.Weh1 = (const float*)d_in[8];
  p.Weh2 = (const float*)d_in[9];
  p.beh  = (const float*)d_in[10];
  p.Wet1 = (const float*)d_in[11];
  p.Wet2 = (const float*)d_in[12];
  p.bet  = (const float*)d_in[13];
  p.Wxh  = (const float*)d_in[14];
  p.Whh  = (const float*)d_in[15];
  p.bh   = (const float*)d_in[16];
  p.Wdh  = (const float*)d_in[17];
  p.bdh  = (const float*)d_in[18];
  p.Wxt  = (const float*)d_in[19];
  p.Wht  = (const float*)d_in[20];
  p.bt   = (const float*)d_in[21];
  p.Wdt  = (const float*)d_in[22];
  p.bdt  = (const float*)d_in[23];
  p.Wc1  = (const float*)d_in[24];
  p.Wc2  = (const float*)d_in[25];
  p.out  = (float*)d_out;
  p.S    = in_sizes[0];

  scheduler_kernel<<<1, 1024>>>(p.heads, p.tails, p.S);
  init_state_kernel<<<256, 256>>>(p.node_rep, p.cell_head, p.hidden_head,
                                  p.cell_tail, p.hidden_tail);
  main_kernel<<<NBLK, NTHR>>>(p);
}

// round 4
// speedup vs baseline: 1.7118x; 1.7118x over previous
#include <cuda_runtime.h>
#include <math.h>
#include <stdint.h>

// ============================================================================
// DyGNN streaming scan -> wave-parallel batched GEMMs (f32x2 packed FFMA).
//
// Events conflict only when they share a node id. A hash-compaction + peeling
// scheduler buckets steps into waves of mutually independent steps. A
// persistent cooperative kernel (2 blocks/SM, software grid barrier) processes
// each wave with 4 phases: B(edge+cadj GEMMs, gathers fused into staging),
// C(LSTM gate GEMMs), D(elementwise gates + state scatter), E(combiner GEMMs
// with fused rep scatter).
// ============================================================================

#define MAXS   2048
#define HSIZE  6144
#define NBLK   296
#define NTHR   256

#define EPI_NONE 0
#define EPI_TANH 1
#define EPI_CADJ 2

typedef unsigned long long ull;

struct Params {
  const int   *heads, *tails;
  const float *times;
  const float *node_rep, *cell_head, *hidden_head, *cell_tail, *hidden_tail;
  const float *Weh1, *Weh2, *beh, *Wet1, *Wet2, *bet;
  const float *Wxh, *Whh, *bh, *Wdh, *bdh;
  const float *Wxt, *Wht, *bt, *Wdt, *bdt;
  const float *Wc1, *Wc2;
  float *out;
  int S;
};

// ---------------- scheduler outputs ----------------
__device__ int g_cidH[MAXS], g_cidT[MAXS];
__device__ int g_slotNode[HSIZE];
__device__ int g_stepList[MAXS];
__device__ int g_waveOff[MAXS + 2];
__device__ int g_numWaves;

// ---------------- compact state tables (indexed by hash slot) --------------
__device__ float c_rep[HSIZE * 128];
__device__ float c_ch [HSIZE * 128];
__device__ float c_hh [HSIZE * 128];
__device__ float c_ct [HSIZE * 128];
__device__ float c_ht [HSIZE * 128];
__device__ float c_rt [HSIZE];

// ---------------- per-wave batch buffers (wave-local row index) -------------
__device__ float bEdgeH[MAXS * 128], bEdgeT[MAXS * 128];
__device__ float bCadjH[MAXS * 128], bCadjT[MAXS * 128];
__device__ float bHTh  [MAXS * 128], bHHt  [MAXS * 128];
__device__ float bHnH  [MAXS * 128], bHnT  [MAXS * 128];
__device__ float bZH   [MAXS * 512], bZT   [MAXS * 512];

// ---------------- grid barrier ----------------
__device__ unsigned g_barCnt;            // zero-init
__device__ volatile unsigned g_barGen;   // zero-init

__device__ __forceinline__ void grid_barrier() {
  __syncthreads();
  if (threadIdx.x == 0) {
    unsigned gen = g_barGen;
    __threadfence();
    if (atomicAdd(&g_barCnt, 1u) == gridDim.x - 1) {
      g_barCnt = 0;
      __threadfence();
      g_barGen = gen + 1;
    } else {
      while (g_barGen == gen) { __nanosleep(64); }
    }
    __threadfence();
  }
  __syncthreads();
}

__device__ __forceinline__ float sigf(float x) { return 1.0f / (1.0f + expf(-x)); }

__device__ __forceinline__ void FFMA2(ull &d, ull a, ull b) {
  asm("fma.rn.f32x2 %0, %1, %2, %0;" : "+l"(d) : "l"(a), "l"(b));
}

// ============================================================================
// Scheduler: hash compaction + peeling into waves. One block, 1024 threads.
// ============================================================================
__global__ void __launch_bounds__(1024) scheduler_kernel(const int* heads, const int* tails, int S) {
  __shared__ int buf[HSIZE];                       // hash table, then nodeMin
  __shared__ unsigned short sCH[MAXS], sCT[MAXS];
  __shared__ unsigned char asg[MAXS];
  __shared__ int sCnt, sBase, sW, sRemain;

  const int tid = threadIdx.x;

  for (int i = tid; i < HSIZE; i += 1024) { buf[i] = 0; g_slotNode[i] = -1; }
  for (int s = tid; s < S; s += 1024) asg[s] = 0;
  if (tid == 0) { sBase = 0; sW = 0; sRemain = S; }
  __syncthreads();

  // ---- insertion: slot = compact id ----
  for (int i = tid; i < 2 * S; i += 1024) {
    int step = i >> 1, isT = i & 1;
    int node = isT ? tails[step] : heads[step];
    int key = node + 1;
    unsigned slot = ((unsigned)node * 2654435761u) % HSIZE;
    while (true) {
      int cur = buf[slot];
      if (cur == key) break;
      if (cur == 0) {
        int old = atomicCAS(&buf[slot], 0, key);
        if (old == 0 || old == key) break;
      }
      slot = (slot + 1u) % HSIZE;
    }
    if (isT) { sCT[step] = (unsigned short)slot; g_cidT[step] = (int)slot; }
    else     { sCH[step] = (unsigned short)slot; g_cidH[step] = (int)slot; }
    g_slotNode[slot] = node;
  }
  __syncthreads();

  // ---- peeling: repeatedly extract all steps whose touches are minimal ----
  while (sRemain > 0) {
    // reset nodeMin for slots of unassigned steps
    for (int s = tid; s < S; s += 1024)
      if (!asg[s]) { buf[sCH[s]] = 0x7FFFFFFF; buf[sCT[s]] = 0x7FFFFFFF; }
    __syncthreads();
    for (int s = tid; s < S; s += 1024)
      if (!asg[s]) {
        atomicMin(&buf[sCH[s]], 2 * s);
        atomicMin(&buf[sCT[s]], 2 * s + 1);
      }
    if (tid == 0) sCnt = 0;
    __syncthreads();
    for (int s = tid; s < S; s += 1024)
      if (!asg[s]) {
        int ch = sCH[s], ct = sCT[s];
        if (buf[ch] == 2 * s && (ct == ch || buf[ct] == 2 * s + 1)) {
          asg[s] = 1;
          int pos = atomicAdd(&sCnt, 1);
          g_stepList[sBase + pos] = s;
        }
      }
    __syncthreads();
    if (tid == 0) {
      g_waveOff[sW] = sBase;
      sBase += sCnt;
      sRemain -= sCnt;
      sW += 1;
      g_waveOff[sW] = sBase;
    }
    __syncthreads();
  }
  if (tid == 0) g_numWaves = sW;
}

// ============================================================================
// Initial gather of touched rows into compact tables.
// ============================================================================
__global__ void init_state_kernel(const float* rep, const float* ch, const float* hh,
                                  const float* ct, const float* ht) {
  int gsize = gridDim.x * blockDim.x;
  for (int e = blockIdx.x * blockDim.x + threadIdx.x; e < HSIZE * 128; e += gsize) {
    int slot = e >> 7, d = e & 127;
    int node = g_slotNode[slot];
    if (node < 0) continue;
    size_t src = (size_t)node * 128 + d;
    c_rep[e] = rep[src];
    c_ch[e]  = ch[src];
    c_hh[e]  = hh[src];
    c_ct[e]  = ct[src];
    c_ht[e]  = ht[src];
    if (d == 0) c_rt[slot] = 0.0f;
  }
}

// ============================================================================
// 32x128 GEMM tile, f32x2 packed FFMA, 4x4 micro-tile per thread (256 thr).
// Y[tile] = epi( A1@W1 (+ A2@W2) + bias ), K=128 per operand pair.
// A rows come through per-row pointers (fused gather); output through per-row
// pointers (fused scatter; null => skip row).
// ============================================================================
__device__ void gemm_tile(const float* __restrict__ W1, const float* __restrict__ W2,
                          bool dual, int ldw, int n0,
                          const float* __restrict__ bias, int epi,
                          const float* const* sA1, const float* const* sA2,
                          float* const* sOut, const float* sDec,
                          float (*AsT2)[64], float (*Ws)[128]) {
  const int tid = threadIdx.x;
  const int tr4 = (tid >> 5) << 2;   // warp id * 4 -> 4 rows
  const int tc  = tid & 31;          // lane -> 4 cols at tc*4

  ull acc[4][2];
#pragma unroll
  for (int i = 0; i < 4; i++) { acc[i][0] = 0ull; acc[i][1] = 0ull; }

  const int rr = tid & 31;
  const int kq = (tid >> 5) << 2;

  const int npair = dual ? 2 : 1;
  for (int pair = 0; pair < npair; ++pair) {
    const float* __restrict__ W = pair ? W2 : W1;
    for (int k0 = 0; k0 < 128; k0 += 32) {
      // stage A (duplicated halves) -- gather via row pointers
      {
        const float* src = pair ? sA2[rr] : sA1[rr];
        float4 av = *(const float4*)(src + k0 + kq);
        *(float2*)&AsT2[kq + 0][2 * rr] = make_float2(av.x, av.x);
        *(float2*)&AsT2[kq + 1][2 * rr] = make_float2(av.y, av.y);
        *(float2*)&AsT2[kq + 2][2 * rr] = make_float2(av.z, av.z);
        *(float2*)&AsT2[kq + 3][2 * rr] = make_float2(av.w, av.w);
      }
      // stage W 32x128
#pragma unroll
      for (int j = 0; j < 4; ++j) {
        int lin = tid + j * NTHR;
        int kk = lin >> 5, c4 = (lin & 31) << 2;
        *(float4*)&Ws[kk][c4] = *(const float4*)(W + (size_t)(k0 + kk) * ldw + n0 + c4);
      }
      __syncthreads();
#pragma unroll
      for (int kk = 0; kk < 32; ++kk) {
        ull a0 = *(const ull*)&AsT2[kk][(tr4 + 0) << 1];
        ull a1 = *(const ull*)&AsT2[kk][(tr4 + 1) << 1];
        ull a2 = *(const ull*)&AsT2[kk][(tr4 + 2) << 1];
        ull a3 = *(const ull*)&AsT2[kk][(tr4 + 3) << 1];
        ulonglong2 w = *(const ulonglong2*)&Ws[kk][tc << 2];
        FFMA2(acc[0][0], a0, w.x); FFMA2(acc[0][1], a0, w.y);
        FFMA2(acc[1][0], a1, w.x); FFMA2(acc[1][1], a1, w.y);
        FFMA2(acc[2][0], a2, w.x); FFMA2(acc[2][1], a2, w.y);
        FFMA2(acc[3][0], a3, w.x); FFMA2(acc[3][1], a3, w.y);
      }
      __syncthreads();
    }
  }

  // epilogue
  union U { ull u; float2 f; };
#pragma unroll
  for (int i = 0; i < 4; i++) {
    int r = tr4 + i;
    float* o = sOut[r];
    if (!o) continue;
    U u0; u0.u = acc[i][0];
    U u1; u1.u = acc[i][1];
    float vals[4] = {u0.f.x, u0.f.y, u1.f.x, u1.f.y};
#pragma unroll
    for (int j = 0; j < 4; j++) {
      int cin = (tc << 2) + j;
      float v = vals[j];
      if (bias) v += bias[cin];
      if (epi == EPI_TANH) {
        v = tanhf(v);
      } else if (epi == EPI_CADJ) {
        float cs = tanhf(v);
        float cp = sA1[r][cin];
        v = cp + cs * (sDec[r] - 1.0f);
      }
      o[cin] = v;
    }
  }
}

// ============================================================================
// Persistent cooperative main kernel. 2 blocks/SM.
// ============================================================================
__global__ void __launch_bounds__(NTHR, 2) main_kernel(Params p) {
  __shared__ float AsT2[32][64];
  __shared__ float Ws[32][128];
  __shared__ const float* sA1[32];
  __shared__ const float* sA2[32];
  __shared__ float* sOut[32];
  __shared__ float sDec[32];

  const int tid = threadIdx.x;
  const int gsize = gridDim.x * blockDim.x;
  const int gtid = blockIdx.x * blockDim.x + tid;
  const int nW = g_numWaves;
  const int S = p.S;

  for (int w = 0; w < nW; ++w) {
    const int s0 = g_waveOff[w];
    const int M = g_waveOff[w + 1] - s0;
    const int mT = (M + 31) >> 5;

    // -------- Phase B: edge + cadj GEMMs, out-emit + stash copies --------
    {
      int nJobs = mT * 5;
      for (int job = blockIdx.x; job < nJobs; job += gridDim.x) {
        int kind = job % 5, mt = job / 5;
        int m0 = mt * 32;
        __syncthreads();
        if (kind == 4) {
          // copy job: out emission + pre-update hidden stash
          for (int l = tid; l < 32 * 32; l += NTHR) {
            int r = l >> 5, q = (l & 31) << 2;
            int m = m0 + r;
            if (m >= M) continue;
            int step = g_stepList[s0 + m];
            int ch = g_cidH[step], ct = g_cidT[step];
            float4 rh = *(const float4*)&c_rep[ch * 128 + q];
            float4 rt = *(const float4*)&c_rep[ct * 128 + q];
            *(float4*)&p.out[(size_t)step * 128 + q] = rh;
            *(float4*)&p.out[(size_t)(S + step) * 128 + q] = rt;
            *(float4*)&bHTh[m * 128 + q] = *(const float4*)&c_ht[ch * 128 + q];
            *(float4*)&bHHt[m * 128 + q] = *(const float4*)&c_hh[ct * 128 + q];
          }
          continue;
        }
        if (tid < 32) {
          int m = m0 + tid;
          bool v = m < M;
          int step = g_stepList[s0 + (v ? m : 0)];
          int ch = g_cidH[step], ct = g_cidT[step];
          const float *a1, *a2 = 0; float* o = 0; float dc = 1.0f;
          if (kind == 0)      { a1 = c_rep + ch * 128; a2 = c_rep + ct * 128; o = bEdgeH + m * 128; }
          else if (kind == 1) { a1 = c_rep + ch * 128; a2 = c_rep + ct * 128; o = bEdgeT + m * 128; }
          else if (kind == 2) { a1 = c_ch + ch * 128; o = bCadjH + m * 128;
                                dc = expf(-(p.times[step] - c_rt[ch])); }
          else                { a1 = c_ct + ct * 128; o = bCadjT + m * 128;
                                dc = expf(-(p.times[step] - c_rt[ct])); }
          sA1[tid] = a1; sA2[tid] = a2; sOut[tid] = v ? o : 0; sDec[tid] = dc;
        }
        __syncthreads();
        if (kind == 0)
          gemm_tile(p.Weh1, p.Weh2, true, 128, 0, p.beh, EPI_TANH, sA1, sA2, sOut, sDec, AsT2, Ws);
        else if (kind == 1)
          gemm_tile(p.Wet1, p.Wet2, true, 128, 0, p.bet, EPI_TANH, sA1, sA2, sOut, sDec, AsT2, Ws);
        else if (kind == 2)
          gemm_tile(p.Wdh, 0, false, 128, 0, p.bdh, EPI_CADJ, sA1, sA2, sOut, sDec, AsT2, Ws);
        else
          gemm_tile(p.Wdt, 0, false, 128, 0, p.bdt, EPI_CADJ, sA1, sA2, sOut, sDec, AsT2, Ws);
      }
    }
    grid_barrier();

    // -------- Phase C: LSTM gate GEMMs (z = edge@Wx + h@Wh + b), N=512 -----
    {
      int nJobs = mT * 8;
      for (int job = blockIdx.x; job < nJobs; job += gridDim.x) {
        int kk2 = job % 8, mt = job / 8;
        int side = kk2 & 1, nt = kk2 >> 1;
        int m0 = mt * 32, n0 = nt * 128;
        __syncthreads();
        if (tid < 32) {
          int m = m0 + tid;
          bool v = m < M;
          int step = g_stepList[s0 + (v ? m : 0)];
          if (side == 0) {
            int ch = g_cidH[step];
            sA1[tid] = bEdgeH + m * 128;
            sA2[tid] = c_hh + ch * 128;
            sOut[tid] = v ? (bZH + m * 512 + n0) : 0;
          } else {
            int ct = g_cidT[step];
            sA1[tid] = bEdgeT + m * 128;
            sA2[tid] = c_ht + ct * 128;
            sOut[tid] = v ? (bZT + m * 512 + n0) : 0;
          }
        }
        __syncthreads();
        if (side == 0)
          gemm_tile(p.Wxh, p.Whh, true, 512, n0, p.bh + n0, EPI_NONE, sA1, sA2, sOut, sDec, AsT2, Ws);
        else
          gemm_tile(p.Wxt, p.Wht, true, 512, n0, p.bt + n0, EPI_NONE, sA1, sA2, sOut, sDec, AsT2, Ws);
      }
    }
    grid_barrier();

    // -------- Phase D: gates elementwise + cell/hidden/rt scatter ---------
    for (int e = gtid; e < M * 128; e += gsize) {
      int s = e >> 7, d = e & 127;
      int step = g_stepList[s0 + s];
      int ch = g_cidH[step], ct = g_cidT[step];
      {
        float zi = bZH[s * 512 + d];
        float zf = bZH[s * 512 + 128 + d];
        float zo = bZH[s * 512 + 256 + d];
        float zg = bZH[s * 512 + 384 + d];
        float ii = sigf(zi), ff = sigf(zf), oo = sigf(zo), gg = tanhf(zg);
        float cn = ff * bCadjH[s * 128 + d] + ii * gg;
        float hn = oo * tanhf(cn);
        bHnH[s * 128 + d] = hn;
        c_ch[ch * 128 + d] = cn;
        c_hh[ch * 128 + d] = hn;
      }
      {
        float zi = bZT[s * 512 + d];
        float zf = bZT[s * 512 + 128 + d];
        float zo = bZT[s * 512 + 256 + d];
        float zg = bZT[s * 512 + 384 + d];
        float ii = sigf(zi), ff = sigf(zf), oo = sigf(zo), gg = tanhf(zg);
        float cn = ff * bCadjT[s * 128 + d] + ii * gg;
        float hn = oo * tanhf(cn);
        bHnT[s * 128 + d] = hn;
        c_ct[ct * 128 + d] = cn;
        c_ht[ct * 128 + d] = hn;
      }
      if (d == 0) {
        float tm = p.times[step];
        c_rt[ch] = tm;
        c_rt[ct] = tm;
      }
    }
    grid_barrier();

    // -------- Phase E: combiner GEMMs with fused rep scatter ---------------
    {
      int nJobs = mT * 2;
      for (int job = blockIdx.x; job < nJobs; job += gridDim.x) {
        int side = job % 2, mt = job / 2;
        int m0 = mt * 32;
        __syncthreads();
        if (tid < 32) {
          int m = m0 + tid;
          bool v = m < M;
          int step = g_stepList[s0 + (v ? m : 0)];
          int ch = g_cidH[step], ct = g_cidT[step];
          if (side == 0) {
            sA1[tid] = bHnH + m * 128;
            sA2[tid] = bHTh + m * 128;
            sOut[tid] = (v && ch != ct) ? (c_rep + ch * 128) : 0;  // tail wins on h==t
          } else {
            sA1[tid] = bHHt + m * 128;
            sA2[tid] = bHnT + m * 128;
            sOut[tid] = v ? (c_rep + ct * 128) : 0;
          }
        }
        __syncthreads();
        gemm_tile(p.Wc1, p.Wc2, true, 128, 0, 0, EPI_TANH, sA1, sA2, sOut, sDec, AsT2, Ws);
      }
    }
    grid_barrier();
  }
}

// ============================================================================
extern "C" void kernel_launch(void* const* d_in, const int* in_sizes, int n_in,
                              void* d_out, int out_size) {
  Params p;
  p.heads       = (const int*)d_in[0];
  p.tails       = (const int*)d_in[1];
  p.times       = (const float*)d_in[2];
  p.node_rep    = (const float*)d_in[3];
  p.cell_head   = (const float*)d_in[4];
  p.hidden_head = (const float*)d_in[5];
  p.cell_tail   = (const float*)d_in[6];
  p.hidden_tail = (const float*)d_in[7];
  p.Weh1 = (const float*)d_in[8];
  p.Weh2 = (const float*)d_in[9];
  p.beh  = (const float*)d_in[10];
  p.Wet1 = (const float*)d_in[11];
  p.Wet2 = (const float*)d_in[12];
  p.bet  = (const float*)d_in[13];
  p.Wxh  = (const float*)d_in[14];
  p.Whh  = (const float*)d_in[15];
  p.bh   = (const float*)d_in[16];
  p.Wdh  = (const float*)d_in[17];
  p.bdh  = (const float*)d_in[18];
  p.Wxt  = (const float*)d_in[19];
  p.Wht  = (const float*)d_in[20];
  p.bt   = (const float*)d_in[21];
  p.Wdt  = (const float*)d_in[22];
  p.bdt  = (const float*)d_in[23];
  p.Wc1  = (const float*)d_in[24];
  p.Wc2  = (const float*)d_in[25];
  p.out  = (float*)d_out;
  p.S    = in_sizes[0];

  scheduler_kernel<<<1, 1024>>>(p.heads, p.tails, p.S);
  init_state_kernel<<<192, 256>>>(p.node_rep, p.cell_head, p.hidden_head,
                                  p.cell_tail, p.hidden_tail);
  main_kernel<<<NBLK, NTHR>>>(p);
}